// round 15
// baseline (speedup 1.0000x reference)
#include <cuda_runtime.h>
#include <cstdint>

#define BB 8
#define NN 65536
#define CC 512
#define DD 128
#define ITERS 10
#define TILE_P 128
#define QSTRIDE 516            // words per point-quad row (bank-staggered)
#define CROW 64                // words per k-row: 32 centers duplicated (v,v)
#define SEG 64                 // sort segments per batch
#define SEGN (NN/SEG)          // 1024 points per segment

// smem: points 32*516, ONE 32KB center buffer, cnorm 512 (~98.5KB -> 2 CTA/SM)
#define SMEM_BYTES ((32*QSTRIDE + 128*CROW + CC) * 4)

__device__ float g_centers[BB*CC*DD];
__device__ float g_cTd[BB*16*DD*CROW];  // [b][chunk32][k][2c] dup'd centers
__device__ float g_cnorm[BB*CC];
__device__ float g_t1[BB*NN];
__device__ int   g_assign[BB*NN];
__device__ int   g_list[BB*NN];
__device__ int   g_off[BB*CC];
__device__ int   g_cnt[BB*CC];
__device__ int   g_hist[BB*SEG*CC];
__device__ int   g_segoff[BB*SEG*CC];

__device__ __forceinline__ void fma2(unsigned long long &d,
                                     unsigned long long a,
                                     unsigned long long b) {
    asm("fma.rn.f32x2 %0, %1, %2, %0;" : "+l"(d) : "l"(a), "l"(b));
}

// ---------------- exact-arithmetic building blocks (DO NOT REORDER) --------
// LLVM-style vectorized sum of v[k]^2: VF=4, IC=2, fma, lanewise, faddp.
__device__ __forceinline__ float norm128_llvm(const float* __restrict__ v) {
    float A0=0.f,A1=0.f,A2=0.f,A3=0.f;
    float B0=0.f,B1=0.f,B2=0.f,B3=0.f;
    #pragma unroll
    for (int i = 0; i < 16; i++) {
        const float* p = v + 8*i;
        A0 = __fmaf_rn(p[0], p[0], A0);
        A1 = __fmaf_rn(p[1], p[1], A1);
        A2 = __fmaf_rn(p[2], p[2], A2);
        A3 = __fmaf_rn(p[3], p[3], A3);
        B0 = __fmaf_rn(p[4], p[4], B0);
        B1 = __fmaf_rn(p[5], p[5], B1);
        B2 = __fmaf_rn(p[6], p[6], B2);
        B3 = __fmaf_rn(p[7], p[7], B3);
    }
    float S0 = __fadd_rn(A0, B0);
    float S1 = __fadd_rn(A1, B1);
    float S2 = __fadd_rn(A2, B2);
    float S3 = __fadd_rn(A3, B3);
    return __fadd_rn(__fadd_rn(S0, S1), __fadd_rn(S2, S3));
}

// ---------------------------------------------------------------------------
__global__ void k_init(const float* __restrict__ centersIn) {
    int i = blockIdx.x * blockDim.x + threadIdx.x;
    if (i < BB*CC*DD) g_centers[i] = centersIn[i];
}
__global__ void k_t1(const float* __restrict__ data) {
    int i = blockIdx.x * blockDim.x + threadIdx.x;
    if (i >= BB*NN) return;
    g_t1[i] = norm128_llvm(data + (size_t)i * DD);
}
__global__ void k_prep() {
    int i = blockIdx.x * blockDim.x + threadIdx.x;
    if (i >= BB*CC) return;
    g_cnorm[i] = norm128_llvm(g_centers + (size_t)i * DD);
}

// k-major chunked transpose with duplication:
// g_cTd[b][c>>5][k][2*(c&31)+{0,1}] = g_centers[b][c][k]
__global__ void k_transpose() {
    int i = blockIdx.x * blockDim.x + threadIdx.x;
    if (i >= BB*CC*DD) return;
    int k = i & 127;
    int c = (i >> 7) & 511;
    int b = i >> 16;
    float v = g_centers[i];
    float2* dst = (float2*)(g_cTd +
        ((((size_t)(b*16 + (c >> 5))*DD + k) << 6) + 2*(c & 31)));
    *dst = make_float2(v, v);
}

// ---------------------------------------------------------------------------
// Assign: exact fp32 fma2 chains, all 512 centers in 16 chunks of 32
// pre-duplicated centers (no dup movs); next chunk prefetched into registers.
// grid=(N/128,B), block=256, 2 CTA/SM, per thread: 8 points x 2 centers/chunk.
__global__ void __launch_bounds__(256, 2) k_assign(const float* __restrict__ data) {
    extern __shared__ float sm[];
    float* ptsS = sm;                       // [32 quads][QSTRIDE]
    float* cenB = ptsS + 32*QSTRIDE;        // [128 k][CROW] dup'd pairs
    float* cnS  = cenB + 128*CROW;          // [512]

    const int b  = blockIdx.y;
    const int n0 = blockIdx.x * TILE_P;
    const int tid = threadIdx.x;
    const int pg = tid >> 4;   // 0..15: points 8pg..8pg+7 (quads 2pg,2pg+1)
    const int cg = tid & 15;   // 0..15: centers 2cg, 2cg+1 within chunk

    for (int i = tid; i < CC; i += 256) cnS[i] = g_cnorm[b*CC + i];

    // point tile, quad-packed: ptsS[p>>2][4k + (p&3)] = x_p[k]
    const float* dptr = data + ((size_t)b*NN + n0) * DD;
    for (int idx = tid; idx < TILE_P*32; idx += 256) {
        int p = idx >> 5;
        int q = idx & 31;
        float4 v = __ldg((const float4*)(dptr + (size_t)p*DD) + q);
        float* dst = ptsS + (p >> 2)*QSTRIDE + (p & 3);
        int k4 = q * 4;
        dst[(k4+0)*4] = v.x; dst[(k4+1)*4] = v.y;
        dst[(k4+2)*4] = v.z; dst[(k4+3)*4] = v.w;
    }

    float t1r[8];
    #pragma unroll
    for (int i = 0; i < 8; i++) t1r[i] = g_t1[b*NN + n0 + 8*pg + i];

    float bv[8]; int bi[8];
    #pragma unroll
    for (int i = 0; i < 8; i++) { bv[i] = 3.4e38f; bi[i] = 0; }

    const float4* csrc4 = (const float4*)(g_cTd + (size_t)b*16*DD*CROW);

    // prefetch chunk 0 into registers (32KB = 2048 float4, 8 per thread)
    float4 pre[8];
    #pragma unroll
    for (int j = 0; j < 8; j++)
        pre[j] = __ldg(csrc4 + j*256 + tid);

    const float* q0p = ptsS + (2*pg)*QSTRIDE;
    const float* q1p = q0p + QSTRIDE;
    const float* cw = cenB + 4*cg;

    for (int ch = 0; ch < 16; ch++) {
        __syncthreads();   // prior chunk's compute done before overwrite
        #pragma unroll
        for (int j = 0; j < 8; j++)
            *(float4*)(cenB + (j*256 + tid)*4) = pre[j];
        __syncthreads();   // chunk visible to all warps

        if (ch < 15) {     // prefetch next chunk; latency hidden by compute
            const float4* src = csrc4 + (size_t)(ch + 1)*2048;
            #pragma unroll
            for (int j = 0; j < 8; j++)
                pre[j] = __ldg(src + j*256 + tid);
        }

        unsigned long long acc[4][2];   // [point pair][center j]
        #pragma unroll
        for (int q = 0; q < 4; q++) { acc[q][0] = 0ull; acc[q][1] = 0ull; }

        #pragma unroll 4
        for (int k = 0; k < DD; k++) {
            ulonglong2 Q0 = *(const ulonglong2*)(q0p + 4*k);  // pts 8pg..+3
            ulonglong2 Q1 = *(const ulonglong2*)(q1p + 4*k);  // pts 8pg+4..+7
            ulonglong2 C  = *(const ulonglong2*)(cw + k*CROW); // dup'd pair x2
            fma2(acc[0][0], Q0.x, C.x); fma2(acc[1][0], Q0.y, C.x);
            fma2(acc[2][0], Q1.x, C.x); fma2(acc[3][0], Q1.y, C.x);
            fma2(acc[0][1], Q0.x, C.y); fma2(acc[1][1], Q0.y, C.y);
            fma2(acc[2][1], Q1.x, C.y); fma2(acc[3][1], Q1.y, C.y);
        }

        // epilogue: s = (t1 - 2*dot) + cn, rn ops in reference association
        int c0 = ch * 32 + 2*cg;
        #pragma unroll
        for (int j = 0; j < 2; j++) {
            int cidx = c0 + j;
            float cn = cnS[cidx];
            #pragma unroll
            for (int q = 0; q < 4; q++) {
                float2 f = *(float2*)&acc[q][j];
                float slo = __fadd_rn(__fsub_rn(t1r[2*q],
                                      __fmul_rn(2.0f, f.x)), cn);
                float shi = __fadd_rn(__fsub_rn(t1r[2*q+1],
                                      __fmul_rn(2.0f, f.y)), cn);
                if (slo < bv[2*q])   { bv[2*q]   = slo; bi[2*q]   = cidx; }
                if (shi < bv[2*q+1]) { bv[2*q+1] = shi; bi[2*q+1] = cidx; }
            }
        }
    }

    // argmin across the 16 cg-lanes per point (tie -> lowest index)
    #pragma unroll
    for (int i = 0; i < 8; i++) {
        float v = bv[i]; int ix = bi[i];
        #pragma unroll
        for (int off = 1; off <= 8; off <<= 1) {
            float ov = __shfl_xor_sync(0xffffffffu, v, off);
            int   oi = __shfl_xor_sync(0xffffffffu, ix, off);
            if (ov < v || (ov == v && oi < ix)) { v = ov; ix = oi; }
        }
        if (cg == 0) g_assign[b*NN + n0 + 8*pg + i] = ix;
    }
}

// ---------------------------------------------------------------------------
// Parallel stable counting sort, 3 phases. Order identical to a single
// ascending-n scan: segment asc, warp asc, lane asc.
// Phase A: per-segment histogram. grid (SEG, BB), block 1024.
__global__ void k_hist() {
    __shared__ int h[CC];
    int b = blockIdx.y, seg = blockIdx.x, tid = threadIdx.x;
    int lane = tid & 31;
    if (tid < CC) h[tid] = 0;
    __syncthreads();
    int a = g_assign[b*NN + seg*SEGN + tid];
    unsigned mask = __match_any_sync(0xffffffffu, a);
    int rank = __popc(mask & ((1u << lane) - 1u));
    if (rank == 0) atomicAdd(&h[a], __popc(mask));
    __syncthreads();
    if (tid < CC) g_hist[(b*SEG + seg)*CC + tid] = h[tid];
}

// Phase B: per-(b,c) prefix over segments + per-batch offsets. grid BB, 512.
__global__ void k_scan() {
    __shared__ int tot[CC];
    int b = blockIdx.x, c = threadIdx.x;
    int run = 0;
    for (int s = 0; s < SEG; s++) {
        int t = g_hist[(b*SEG + s)*CC + c];
        g_segoff[(b*SEG + s)*CC + c] = run;
        run += t;
    }
    tot[c] = run;
    g_cnt[b*CC + c] = run;
    __syncthreads();
    if (c == 0) {
        int r2 = 0;
        for (int i = 0; i < CC; i++) {
            g_off[b*CC + i] = r2;
            r2 += tot[i];
        }
    }
}

// Phase C: stable scatter. grid (SEG, BB), block 1024, 64KB dyn smem.
__global__ void k_scatter() {
    extern __shared__ int W[];   // [32 warps][CC]
    int b = blockIdx.y, seg = blockIdx.x, tid = threadIdx.x;
    int w = tid >> 5, lane = tid & 31;
    for (int i = tid; i < 32*CC; i += 1024) W[i] = 0;
    __syncthreads();
    int n = seg*SEGN + tid;
    int a = g_assign[b*NN + n];
    unsigned mask = __match_any_sync(0xffffffffu, a);
    int rank = __popc(mask & ((1u << lane) - 1u));
    if (rank == 0) W[w*CC + a] = __popc(mask);
    __syncthreads();
    if (tid < CC) {
        int s = 0;
        for (int ww = 0; ww < 32; ww++) {
            int t = W[ww*CC + tid];
            W[ww*CC + tid] = s;
            s += t;
        }
    }
    __syncthreads();
    int pos = g_off[b*CC + a] + g_segoff[(b*SEG + seg)*CC + a]
            + W[w*CC + a] + rank;
    g_list[b*NN + pos] = n;
}

// ---------------------------------------------------------------------------
// New centers: sequential ascending-n fp32 adds per (b,c,d), then rn divide.
// Unrolled x8: loads batched (independent), adds strictly in ascending order.
__global__ void k_update(const float* __restrict__ data) {
    __shared__ int listS[128];
    int c = blockIdx.x, b = blockIdx.y, d = threadIdx.x;
    int off = g_off[b*CC + c];
    int cnt = g_cnt[b*CC + c];
    const float* db = data + (size_t)b*NN*DD + d;
    float acc = 0.f;
    for (int base = 0; base < cnt; base += 128) {
        __syncthreads();
        int m = min(128, cnt - base);
        if (d < m) listS[d] = g_list[b*NN + off + base + d];
        __syncthreads();
        int j = 0;
        for (; j + 8 <= m; j += 8) {
            float v0 = __ldg(db + (size_t)listS[j+0]*DD);
            float v1 = __ldg(db + (size_t)listS[j+1]*DD);
            float v2 = __ldg(db + (size_t)listS[j+2]*DD);
            float v3 = __ldg(db + (size_t)listS[j+3]*DD);
            float v4 = __ldg(db + (size_t)listS[j+4]*DD);
            float v5 = __ldg(db + (size_t)listS[j+5]*DD);
            float v6 = __ldg(db + (size_t)listS[j+6]*DD);
            float v7 = __ldg(db + (size_t)listS[j+7]*DD);
            acc = __fadd_rn(acc, v0); acc = __fadd_rn(acc, v1);
            acc = __fadd_rn(acc, v2); acc = __fadd_rn(acc, v3);
            acc = __fadd_rn(acc, v4); acc = __fadd_rn(acc, v5);
            acc = __fadd_rn(acc, v6); acc = __fadd_rn(acc, v7);
        }
        for (; j < m; j++)
            acc = __fadd_rn(acc, __ldg(db + (size_t)listS[j]*DD));
    }
    if (cnt > 0)
        g_centers[(size_t)(b*CC + c)*DD + d] = __fdiv_rn(acc, __int2float_rn(cnt));
}

// d_out = [centers (B*C*D) | (float)assign broadcast over D (B*N*D)]
__global__ void k_output(float* __restrict__ out) {
    size_t i = (size_t)blockIdx.x * blockDim.x + threadIdx.x;
    const size_t nc = (size_t)BB*CC*DD;
    const size_t total = nc + (size_t)BB*NN*DD;
    if (i >= total) return;
    if (i < nc) out[i] = g_centers[i];
    else {
        size_t j = i - nc;
        out[i] = (float)g_assign[j >> 7];
    }
}

// ---------------------------------------------------------------------------
extern "C" void kernel_launch(void* const* d_in, const int* in_sizes, int n_in,
                              void* d_out, int out_size) {
    const float* data      = (const float*)d_in[0];
    const float* centersIn = (const float*)d_in[1];
    float* out = (float*)d_out;

    cudaFuncSetAttribute(k_assign, cudaFuncAttributeMaxDynamicSharedMemorySize,
                         SMEM_BYTES);
    cudaFuncSetAttribute(k_scatter, cudaFuncAttributeMaxDynamicSharedMemorySize,
                         32*CC*(int)sizeof(int));

    k_init<<<(BB*CC*DD + 255)/256, 256>>>(centersIn);
    k_t1<<<(BB*NN + 255)/256, 256>>>(data);
    for (int it = 0; it < ITERS; it++) {
        k_prep<<<(BB*CC + 63)/64, 64>>>();
        k_transpose<<<(BB*CC*DD + 255)/256, 256>>>();
        k_assign<<<dim3(NN/TILE_P, BB), 256, SMEM_BYTES>>>(data);
        k_hist<<<dim3(SEG, BB), 1024>>>();
        k_scan<<<BB, 512>>>();
        k_scatter<<<dim3(SEG, BB), 1024, 32*CC*(int)sizeof(int)>>>();
        k_update<<<dim3(CC, BB), 128>>>(data);
    }
    const size_t total = (size_t)BB*CC*DD + (size_t)BB*NN*DD;
    k_output<<<(unsigned)((total + 255)/256), 256>>>(out);
}

// round 16
// speedup vs baseline: 1.5702x; 1.5702x over previous
#include <cuda_runtime.h>
#include <cstdint>

#define BB 8
#define NN 65536
#define CC 512
#define DD 128
#define ITERS 10
#define TILE_P 128
#define QSTRIDE 516            // words per point-quad row (bank-staggered)
#define CROW 64                // words per k-row of non-dup 64-center chunk
#define SEG 64                 // sort segments per batch
#define SEGN (NN/SEG)          // 1024 points per segment

// smem: points 32*516, ONE 32KB center buffer, cnorm 512 (~98.5KB -> 2 CTA/SM)
#define SMEM_BYTES ((32*QSTRIDE + 128*CROW + CC) * 4)

__device__ float g_centers[BB*CC*DD];
__device__ float g_cT[BB*8*DD*64];      // [b][chunk64][k][c&63] k-major centers
__device__ float g_cnorm[BB*CC];
__device__ float g_t1[BB*NN];
__device__ int   g_assign[BB*NN];
__device__ int   g_list[BB*NN];
__device__ int   g_off[BB*CC];
__device__ int   g_cnt[BB*CC];
__device__ int   g_hist[BB*SEG*CC];
__device__ int   g_segoff[BB*SEG*CC];

__device__ __forceinline__ void fma2(unsigned long long &d,
                                     unsigned long long a,
                                     unsigned long long b) {
    asm("fma.rn.f32x2 %0, %1, %2, %0;" : "+l"(d) : "l"(a), "l"(b));
}
__device__ __forceinline__ unsigned long long dup2(float x) {
    unsigned long long r;
    asm("mov.b64 %0, {%1, %1};" : "=l"(r) : "f"(x));
    return r;
}

// ---------------- exact-arithmetic building blocks (DO NOT REORDER) --------
// LLVM-style vectorized sum of v[k]^2: VF=4, IC=2, fma, lanewise, faddp.
__device__ __forceinline__ float norm128_llvm(const float* __restrict__ v) {
    float A0=0.f,A1=0.f,A2=0.f,A3=0.f;
    float B0=0.f,B1=0.f,B2=0.f,B3=0.f;
    #pragma unroll
    for (int i = 0; i < 16; i++) {
        const float* p = v + 8*i;
        A0 = __fmaf_rn(p[0], p[0], A0);
        A1 = __fmaf_rn(p[1], p[1], A1);
        A2 = __fmaf_rn(p[2], p[2], A2);
        A3 = __fmaf_rn(p[3], p[3], A3);
        B0 = __fmaf_rn(p[4], p[4], B0);
        B1 = __fmaf_rn(p[5], p[5], B1);
        B2 = __fmaf_rn(p[6], p[6], B2);
        B3 = __fmaf_rn(p[7], p[7], B3);
    }
    float S0 = __fadd_rn(A0, B0);
    float S1 = __fadd_rn(A1, B1);
    float S2 = __fadd_rn(A2, B2);
    float S3 = __fadd_rn(A3, B3);
    return __fadd_rn(__fadd_rn(S0, S1), __fadd_rn(S2, S3));
}

// ---------------------------------------------------------------------------
__global__ void k_init(const float* __restrict__ centersIn) {
    int i = blockIdx.x * blockDim.x + threadIdx.x;
    if (i < BB*CC*DD) g_centers[i] = centersIn[i];
}
__global__ void k_t1(const float* __restrict__ data) {
    int i = blockIdx.x * blockDim.x + threadIdx.x;
    if (i >= BB*NN) return;
    g_t1[i] = norm128_llvm(data + (size_t)i * DD);
}
__global__ void k_prep() {
    int i = blockIdx.x * blockDim.x + threadIdx.x;
    if (i >= BB*CC) return;
    g_cnorm[i] = norm128_llvm(g_centers + (size_t)i * DD);
}

// k-major chunked transpose: g_cT[b][c>>6][k][c&63] = g_centers[b][c][k]
__global__ void k_transpose() {
    int i = blockIdx.x * blockDim.x + threadIdx.x;
    if (i >= BB*CC*DD) return;
    int k = i & 127;
    int c = (i >> 7) & 511;
    int b = i >> 16;
    float v = g_centers[i];
    g_cT[(((size_t)(b*8 + (c >> 6))*DD + k) << 6) + (c & 63)] = v;
}

// ---------------------------------------------------------------------------
// Assign: exact fp32 fma2 chains, all 512 centers; next chunk prefetched into
// registers during compute. grid=(N/128,B), block=256, 2 CTA/SM,
// per thread: 8 points x 4 centers.
__global__ void __launch_bounds__(256, 2) k_assign(const float* __restrict__ data) {
    extern __shared__ float sm[];
    float* ptsS = sm;                       // [32 quads][QSTRIDE]
    float* cenB = ptsS + 32*QSTRIDE;        // [128 k][CROW]
    float* cnS  = cenB + 128*CROW;          // [512]

    const int b  = blockIdx.y;
    const int n0 = blockIdx.x * TILE_P;
    const int tid = threadIdx.x;
    const int pg = tid >> 4;   // 0..15: points 8pg..8pg+7 (quads 2pg,2pg+1)
    const int cg = tid & 15;   // 0..15: centers 4cg..4cg+3 within chunk

    for (int i = tid; i < CC; i += 256) cnS[i] = g_cnorm[b*CC + i];

    // point tile, quad-packed: ptsS[p>>2][4k + (p&3)] = x_p[k]
    const float* dptr = data + ((size_t)b*NN + n0) * DD;
    for (int idx = tid; idx < TILE_P*32; idx += 256) {
        int p = idx >> 5;
        int q = idx & 31;
        float4 v = __ldg((const float4*)(dptr + (size_t)p*DD) + q);
        float* dst = ptsS + (p >> 2)*QSTRIDE + (p & 3);
        int k4 = q * 4;
        dst[(k4+0)*4] = v.x; dst[(k4+1)*4] = v.y;
        dst[(k4+2)*4] = v.z; dst[(k4+3)*4] = v.w;
    }

    float t1r[8];
    #pragma unroll
    for (int i = 0; i < 8; i++) t1r[i] = g_t1[b*NN + n0 + 8*pg + i];

    float bv[8]; int bi[8];
    #pragma unroll
    for (int i = 0; i < 8; i++) { bv[i] = 3.4e38f; bi[i] = 0; }

    const float4* csrc4 = (const float4*)(g_cT + (size_t)b*8*DD*64);

    // prefetch chunk 0 into registers (32KB = 2048 float4, 8 per thread)
    float4 pre[8];
    #pragma unroll
    for (int j = 0; j < 8; j++)
        pre[j] = __ldg(csrc4 + j*256 + tid);

    const float* q0p = ptsS + (2*pg)*QSTRIDE;
    const float* q1p = q0p + QSTRIDE;
    const float* cw = cenB + 4*cg;

    for (int ch = 0; ch < 8; ch++) {
        __syncthreads();   // prior chunk's compute done before overwrite
        #pragma unroll
        for (int j = 0; j < 8; j++)
            *(float4*)(cenB + (j*256 + tid)*4) = pre[j];
        __syncthreads();   // chunk visible to all warps

        if (ch < 7) {      // prefetch next chunk; latency hidden by compute
            const float4* src = csrc4 + (size_t)(ch + 1)*2048;
            #pragma unroll
            for (int j = 0; j < 8; j++)
                pre[j] = __ldg(src + j*256 + tid);
        }

        unsigned long long acc[4][4];   // [point pair][center j]
        #pragma unroll
        for (int q = 0; q < 4; q++)
            #pragma unroll
            for (int j = 0; j < 4; j++) acc[q][j] = 0ull;

        #pragma unroll 4
        for (int k = 0; k < DD; k++) {
            ulonglong2 Q0 = *(const ulonglong2*)(q0p + 4*k);  // pts 8pg..+3
            ulonglong2 Q1 = *(const ulonglong2*)(q1p + 4*k);  // pts 8pg+4..+7
            float4 C4 = *(const float4*)(cw + k*CROW);
            unsigned long long c0d = dup2(C4.x), c1d = dup2(C4.y);
            unsigned long long c2d = dup2(C4.z), c3d = dup2(C4.w);
            fma2(acc[0][0], Q0.x, c0d); fma2(acc[1][0], Q0.y, c0d);
            fma2(acc[2][0], Q1.x, c0d); fma2(acc[3][0], Q1.y, c0d);
            fma2(acc[0][1], Q0.x, c1d); fma2(acc[1][1], Q0.y, c1d);
            fma2(acc[2][1], Q1.x, c1d); fma2(acc[3][1], Q1.y, c1d);
            fma2(acc[0][2], Q0.x, c2d); fma2(acc[1][2], Q0.y, c2d);
            fma2(acc[2][2], Q1.x, c2d); fma2(acc[3][2], Q1.y, c2d);
            fma2(acc[0][3], Q0.x, c3d); fma2(acc[1][3], Q0.y, c3d);
            fma2(acc[2][3], Q1.x, c3d); fma2(acc[3][3], Q1.y, c3d);
        }

        // epilogue: s = (t1 - 2*dot) + cn, rn ops in reference association
        int c0 = ch * 64 + 4*cg;
        #pragma unroll
        for (int j = 0; j < 4; j++) {
            int cidx = c0 + j;
            float cn = cnS[cidx];
            #pragma unroll
            for (int q = 0; q < 4; q++) {
                float2 f = *(float2*)&acc[q][j];
                float slo = __fadd_rn(__fsub_rn(t1r[2*q],
                                      __fmul_rn(2.0f, f.x)), cn);
                float shi = __fadd_rn(__fsub_rn(t1r[2*q+1],
                                      __fmul_rn(2.0f, f.y)), cn);
                if (slo < bv[2*q])   { bv[2*q]   = slo; bi[2*q]   = cidx; }
                if (shi < bv[2*q+1]) { bv[2*q+1] = shi; bi[2*q+1] = cidx; }
            }
        }
    }

    // argmin across the 16 cg-lanes per point (tie -> lowest index)
    #pragma unroll
    for (int i = 0; i < 8; i++) {
        float v = bv[i]; int ix = bi[i];
        #pragma unroll
        for (int off = 1; off <= 8; off <<= 1) {
            float ov = __shfl_xor_sync(0xffffffffu, v, off);
            int   oi = __shfl_xor_sync(0xffffffffu, ix, off);
            if (ov < v || (ov == v && oi < ix)) { v = ov; ix = oi; }
        }
        if (cg == 0) g_assign[b*NN + n0 + 8*pg + i] = ix;
    }
}

// ---------------------------------------------------------------------------
// Parallel stable counting sort, 3 phases. Order identical to a single
// ascending-n scan: segment asc, warp asc, lane asc.
// Phase A: per-segment histogram. grid (SEG, BB), block 1024.
__global__ void k_hist() {
    __shared__ int h[CC];
    int b = blockIdx.y, seg = blockIdx.x, tid = threadIdx.x;
    int lane = tid & 31;
    if (tid < CC) h[tid] = 0;
    __syncthreads();
    int a = g_assign[b*NN + seg*SEGN + tid];
    unsigned mask = __match_any_sync(0xffffffffu, a);
    int rank = __popc(mask & ((1u << lane) - 1u));
    if (rank == 0) atomicAdd(&h[a], __popc(mask));
    __syncthreads();
    if (tid < CC) g_hist[(b*SEG + seg)*CC + tid] = h[tid];
}

// Phase B: per-(b,c) prefix over segments + per-batch offsets. grid BB, 512.
__global__ void k_scan() {
    __shared__ int tot[CC];
    int b = blockIdx.x, c = threadIdx.x;
    int run = 0;
    for (int s = 0; s < SEG; s++) {
        int t = g_hist[(b*SEG + s)*CC + c];
        g_segoff[(b*SEG + s)*CC + c] = run;
        run += t;
    }
    tot[c] = run;
    g_cnt[b*CC + c] = run;
    __syncthreads();
    if (c == 0) {
        int r2 = 0;
        for (int i = 0; i < CC; i++) {
            g_off[b*CC + i] = r2;
            r2 += tot[i];
        }
    }
}

// Phase C: stable scatter. grid (SEG, BB), block 1024, 64KB dyn smem.
__global__ void k_scatter() {
    extern __shared__ int W[];   // [32 warps][CC]
    int b = blockIdx.y, seg = blockIdx.x, tid = threadIdx.x;
    int w = tid >> 5, lane = tid & 31;
    for (int i = tid; i < 32*CC; i += 1024) W[i] = 0;
    __syncthreads();
    int n = seg*SEGN + tid;
    int a = g_assign[b*NN + n];
    unsigned mask = __match_any_sync(0xffffffffu, a);
    int rank = __popc(mask & ((1u << lane) - 1u));
    if (rank == 0) W[w*CC + a] = __popc(mask);
    __syncthreads();
    if (tid < CC) {
        int s = 0;
        for (int ww = 0; ww < 32; ww++) {
            int t = W[ww*CC + tid];
            W[ww*CC + tid] = s;
            s += t;
        }
    }
    __syncthreads();
    int pos = g_off[b*CC + a] + g_segoff[(b*SEG + seg)*CC + a]
            + W[w*CC + a] + rank;
    g_list[b*NN + pos] = n;
}

// ---------------------------------------------------------------------------
// New centers: sequential ascending-n fp32 adds per (b,c,d), then rn divide.
// Unrolled x8: loads batched (independent), adds strictly in ascending order.
__global__ void k_update(const float* __restrict__ data) {
    __shared__ int listS[128];
    int c = blockIdx.x, b = blockIdx.y, d = threadIdx.x;
    int off = g_off[b*CC + c];
    int cnt = g_cnt[b*CC + c];
    const float* db = data + (size_t)b*NN*DD + d;
    float acc = 0.f;
    for (int base = 0; base < cnt; base += 128) {
        __syncthreads();
        int m = min(128, cnt - base);
        if (d < m) listS[d] = g_list[b*NN + off + base + d];
        __syncthreads();
        int j = 0;
        for (; j + 8 <= m; j += 8) {
            float v0 = __ldg(db + (size_t)listS[j+0]*DD);
            float v1 = __ldg(db + (size_t)listS[j+1]*DD);
            float v2 = __ldg(db + (size_t)listS[j+2]*DD);
            float v3 = __ldg(db + (size_t)listS[j+3]*DD);
            float v4 = __ldg(db + (size_t)listS[j+4]*DD);
            float v5 = __ldg(db + (size_t)listS[j+5]*DD);
            float v6 = __ldg(db + (size_t)listS[j+6]*DD);
            float v7 = __ldg(db + (size_t)listS[j+7]*DD);
            acc = __fadd_rn(acc, v0); acc = __fadd_rn(acc, v1);
            acc = __fadd_rn(acc, v2); acc = __fadd_rn(acc, v3);
            acc = __fadd_rn(acc, v4); acc = __fadd_rn(acc, v5);
            acc = __fadd_rn(acc, v6); acc = __fadd_rn(acc, v7);
        }
        for (; j < m; j++)
            acc = __fadd_rn(acc, __ldg(db + (size_t)listS[j]*DD));
    }
    if (cnt > 0)
        g_centers[(size_t)(b*CC + c)*DD + d] = __fdiv_rn(acc, __int2float_rn(cnt));
}

// d_out = [centers (B*C*D) | (float)assign broadcast over D (B*N*D)]
__global__ void k_output(float* __restrict__ out) {
    size_t i = (size_t)blockIdx.x * blockDim.x + threadIdx.x;
    const size_t nc = (size_t)BB*CC*DD;
    const size_t total = nc + (size_t)BB*NN*DD;
    if (i >= total) return;
    if (i < nc) out[i] = g_centers[i];
    else {
        size_t j = i - nc;
        out[i] = (float)g_assign[j >> 7];
    }
}

// ---------------------------------------------------------------------------
extern "C" void kernel_launch(void* const* d_in, const int* in_sizes, int n_in,
                              void* d_out, int out_size) {
    const float* data      = (const float*)d_in[0];
    const float* centersIn = (const float*)d_in[1];
    float* out = (float*)d_out;

    cudaFuncSetAttribute(k_assign, cudaFuncAttributeMaxDynamicSharedMemorySize,
                         SMEM_BYTES);
    cudaFuncSetAttribute(k_scatter, cudaFuncAttributeMaxDynamicSharedMemorySize,
                         32*CC*(int)sizeof(int));

    k_init<<<(BB*CC*DD + 255)/256, 256>>>(centersIn);
    k_t1<<<(BB*NN + 255)/256, 256>>>(data);
    for (int it = 0; it < ITERS; it++) {
        k_prep<<<(BB*CC + 63)/64, 64>>>();
        k_transpose<<<(BB*CC*DD + 255)/256, 256>>>();
        k_assign<<<dim3(NN/TILE_P, BB), 256, SMEM_BYTES>>>(data);
        k_hist<<<dim3(SEG, BB), 1024>>>();
        k_scan<<<BB, 512>>>();
        k_scatter<<<dim3(SEG, BB), 1024, 32*CC*(int)sizeof(int)>>>();
        k_update<<<dim3(CC, BB), 128>>>(data);
    }
    const size_t total = (size_t)BB*CC*DD + (size_t)BB*NN*DD;
    k_output<<<(unsigned)((total + 255)/256), 256>>>(out);
}